// round 14
// baseline (speedup 1.0000x reference)
#include <cuda_runtime.h>
#include <cuda_fp16.h>
#include <math.h>
#include <stdint.h>

#define H     1024
#define BATCH 256
#define NCAM  15
#define NT    60
#define G3H   3072

#define TM 32
#define TJ 32
#define TN 96
#define KC 64
#define NK (H/KC)
#define NSA 2
#define NSB 3
#define A_STG 4096
#define B_STG 12288
#define A_RING (NSA*A_STG)            // 8192
#define B_OFF  A_RING
#define B_RING (NSB*B_STG)            // 36864
#define GHS_OFF (B_OFF + B_RING)      // 45056
#define GHS_BYTES (16*104*4)          // 6656
#define BAR_OFF (GHS_OFF + GHS_BYTES) // 51712
#define SMEM_DYN (BAR_OFF + 64)       // 51776 -> 4 CTAs/SM
#define NCTA (32*NCAM)                // 480 == grid size, all resident

// ---------------- scratch (static device globals) ----------------
__device__ __align__(128) char g_Pwih[(size_t)NCAM*32*NK*B_STG];
__device__ __align__(128) char g_Pwhh[(size_t)NCAM*32*NK*B_STG];
__device__ __align__(128) char g_xpack[(size_t)NCAM*2*NK*A_STG];
__device__ __align__(128) char g_hPA [(size_t)NCAM*2*NK*A_STG];
__device__ __align__(128) char g_hPB [(size_t)NCAM*2*NK*A_STG];
__device__ __align__(128) float g_hA[BATCH*H];
__device__ __align__(128) float g_hB[BATCH*H];
__device__ __align__(128) float g_gi[(size_t)BATCH*G3H];
__device__ __align__(128) float g_hs[(size_t)NT*BATCH*H];
__device__ int g_order[BATCH];
__device__ int g_seg[NCAM+1];
__device__ unsigned g_cnt;      // grid barrier counter (zero-init)
__device__ unsigned g_gen;      // grid barrier generation (monotonic)

// ---------------- ptx helpers ----------------
__device__ __forceinline__ void mbar_init(uint32_t a, uint32_t cnt){
    asm volatile("mbarrier.init.shared.b64 [%0], %1;" :: "r"(a), "r"(cnt) : "memory");
}
__device__ __forceinline__ void mbar_expect(uint32_t a, uint32_t tx){
    asm volatile("mbarrier.arrive.expect_tx.shared.b64 _, [%0], %1;" :: "r"(a), "r"(tx) : "memory");
}
__device__ __forceinline__ void bulk_g2s(uint32_t dst, const void* src, uint32_t bytes, uint32_t mbar){
    asm volatile("cp.async.bulk.shared::cta.global.mbarrier::complete_tx::bytes [%0], [%1], %2, [%3];"
                 :: "r"(dst), "l"(src), "r"(bytes), "r"(mbar) : "memory");
}
__device__ __forceinline__ void mbar_wait(uint32_t a, uint32_t phase){
    asm volatile("{\n\t.reg .pred P;\n\t"
                 "WL_%=:\n\t"
                 "mbarrier.try_wait.parity.acquire.cta.shared::cta.b64 P, [%0], %1, 0x989680;\n\t"
                 "@P bra.uni WD_%=;\n\t"
                 "bra.uni WL_%=;\n\t"
                 "WD_%=:\n\t}"
                 :: "r"(a), "r"(phase) : "memory");
}
__device__ __forceinline__ float sigf(float x){ return 1.f/(1.f + __expf(-x)); }
__device__ __forceinline__ float tanhfast(float x){ return 2.f/(1.f + __expf(-2.f*x)) - 1.f; }

// sense-reversing grid barrier (all NCTA CTAs resident by construction)
__device__ __forceinline__ void grid_barrier(int tid){
    __syncthreads();
    if (tid == 0){
        __threadfence();
        asm volatile("fence.proxy.async;" ::: "memory");
        unsigned gen = *(volatile unsigned*)&g_gen;
        unsigned prev = atomicAdd(&g_cnt, 1);
        if (prev == NCTA - 1){
            atomicExch(&g_cnt, 0);
            __threadfence();
            atomicAdd(&g_gen, 1);
        } else {
            while (*(volatile unsigned*)&g_gen == gen) __nanosleep(64);
        }
        __threadfence();
    }
    __syncthreads();
}

// ---------------- setup: group samples by camera ----------------
__global__ void setup_kernel(const int* __restrict__ cam){
    __shared__ int cnt[NCAM], offs[NCAM];
    int tid = threadIdx.x;
    if (tid < NCAM) cnt[tid] = 0;
    __syncthreads();
    int c = cam[tid];
    atomicAdd(&cnt[c], 1);
    __syncthreads();
    if (tid == 0){
        int s = 0;
        for (int i = 0; i < NCAM; i++){ offs[i] = s; g_seg[i] = s; s += cnt[i]; }
        g_seg[NCAM] = s;
    }
    __syncthreads();
    int p = atomicAdd(&offs[c], 1);
    g_order[p] = tid;
}

// ---------------- init: pack x (sorted+swizzled), zero hP/hA ----------------
#define XCH   (NCAM*2*NK*256)
#define HPCH  (NCAM*2*NK*256)
__global__ void init_pack_kernel(const float* __restrict__ x){
    const int total = XCH + 2*HPCH + BATCH*H/4;
    int stride = gridDim.x*blockDim.x;
    for (int i = blockIdx.x*blockDim.x + threadIdx.x; i < total; i += stride){
        if (i < XCH){
            int blk = i >> 8, cin = i & 255;
            int r = cin >> 3, ch = cin & 7;
            int kt = blk & 15, cm = blk >> 4;
            int mt = cm & 1, c = cm >> 1;
            int seg0 = g_seg[c], bc = g_seg[c+1]-seg0;
            int mg = mt*TM + r;
            uint4 v = make_uint4(0,0,0,0);
            if (mg < bc){
                int bidx = g_order[seg0+mg];
                const float4* s = (const float4*)(x + (size_t)bidx*H + kt*KC + ch*8);
                float4 a = s[0], b = s[1];
                __half2 h0 = __floats2half2_rn(a.x,a.y), h1 = __floats2half2_rn(a.z,a.w);
                __half2 h2 = __floats2half2_rn(b.x,b.y), h3 = __floats2half2_rn(b.z,b.w);
                v.x = *(uint32_t*)&h0; v.y = *(uint32_t*)&h1;
                v.z = *(uint32_t*)&h2; v.w = *(uint32_t*)&h3;
            }
            *(uint4*)(g_xpack + (size_t)blk*A_STG + r*128 + ((ch ^ (r&7))<<4)) = v;
        } else if (i < XCH + 2*HPCH){
            int k = i - XCH;
            if (k < HPCH) ((uint4*)g_hPA)[k] = make_uint4(0,0,0,0);
            else          ((uint4*)g_hPB)[k-HPCH] = make_uint4(0,0,0,0);
        } else {
            int k = i - XCH - 2*HPCH;
            ((float4*)g_hA)[k] = make_float4(0.f,0.f,0.f,0.f);
        }
    }
}

// ---------------- convert + pack weights fp32 -> fp16 swizzled tiles ----------------
__global__ void convert_pack_kernel(const float* __restrict__ wi, const float* __restrict__ wh){
    const size_t NCH = (size_t)NCAM*32*NK*768;
    size_t stride = (size_t)gridDim.x*blockDim.x;
    for (size_t i = (size_t)blockIdx.x*blockDim.x + threadIdx.x; i < NCH; i += stride){
        size_t blk = i / 768; int cin = (int)(i % 768);
        int r = cin >> 3, ch = cin & 7;
        int kt = (int)(blk & 15); size_t cj = blk >> 4;
        int jt = (int)(cj & 31); int c = (int)(cj >> 5);
        int grow = ((r>>5)<<10) + jt*TJ + (r & 31);
        size_t src = (((size_t)c*G3H + grow)<<10) + kt*KC + ch*8;
        size_t dst = blk*B_STG + r*128 + ((ch ^ (r&7))<<4);
        {
            const float4* s = (const float4*)(wi + src);
            float4 a = __ldcs(s), b = __ldcs(s+1);
            __half2 h0 = __floats2half2_rn(a.x,a.y), h1 = __floats2half2_rn(a.z,a.w);
            __half2 h2 = __floats2half2_rn(b.x,b.y), h3 = __floats2half2_rn(b.z,b.w);
            uint4 v; v.x=*(uint32_t*)&h0; v.y=*(uint32_t*)&h1; v.z=*(uint32_t*)&h2; v.w=*(uint32_t*)&h3;
            __stcs((uint4*)(g_Pwih + dst), v);
        }
        {
            const float4* s = (const float4*)(wh + src);
            float4 a = __ldcs(s), b = __ldcs(s+1);
            __half2 h0 = __floats2half2_rn(a.x,a.y), h1 = __floats2half2_rn(a.z,a.w);
            __half2 h2 = __floats2half2_rn(b.x,b.y), h3 = __floats2half2_rn(b.z,b.w);
            uint4 v; v.x=*(uint32_t*)&h0; v.y=*(uint32_t*)&h1; v.z=*(uint32_t*)&h2; v.w=*(uint32_t*)&h3;
            *(uint4*)(g_Pwhh + dst) = v;
        }
    }
}

// ---------------- persistent kernel: gi phase + all 60 GRU steps ----------------
// grid (32, 15) = 480 CTAs, all resident. B (weight) pipeline runs CONTINUOUSLY
// across step barriers (weights constant per step); only A restarts per step.
__global__ void __launch_bounds__(256, 4) persistent_kernel(const float* __restrict__ b_ih,
                                                            const float* __restrict__ b_hh)
{
    extern __shared__ __align__(128) char smem[];
    const int jt = blockIdx.x, c = blockIdx.y;
    const int tid = threadIdx.x, lane = tid & 31, warp = tid >> 5;
    const int wm = warp & 1, wn = warp >> 1;
    const int seg0 = g_seg[c], bc = g_seg[c+1] - seg0;
    const int nmt = (bc + TM - 1) / TM;     // 0..2
    const int j0 = jt*TJ;
    uint32_t smem_u32 = (uint32_t)__cvta_generic_to_shared(smem);
    uint32_t mbFA = smem_u32 + BAR_OFF;     // fullA[2]
    uint32_t mbFB = mbFA + 16;              // fullB[3]

    if (tid == 0){
        mbar_init(mbFA, 1); mbar_init(mbFA + 8, 1);
        #pragma unroll
        for (int s = 0; s < NSB; s++) mbar_init(mbFB + s*8, 1);
        asm volatile("fence.proxy.async.shared::cta;" ::: "memory");
    }
    __syncthreads();

    const unsigned totalB = (unsigned)(NT + 1) * NK * nmt;
    const size_t bOffW = (size_t)(c*32 + jt) * NK * B_STG;
    unsigned gBi = 0;                       // tid0-only B issue counter

    auto issueB = [&](){
        if (gBi < totalB){
            int s = gBi % NSB;
            int ka = gBi & (NK - 1);
            const char* bp = (gBi < (unsigned)(NK*nmt)) ? g_Pwih : g_Pwhh;
            mbar_expect(mbFB + s*8, B_STG);
            bulk_g2s(smem_u32 + B_OFF + s*B_STG, bp + bOffW + (size_t)ka*B_STG, B_STG, mbFB + s*8);
            gBi++;
        }
    };
    auto issueA = [&](int slot, int p, int mt, int ka){
        const char* base = (p == 0) ? g_xpack : (((p-1) & 1) ? g_hPB : g_hPA);
        mbar_expect(mbFA + slot*8, A_STG);
        bulk_g2s(smem_u32 + slot*A_STG,
                 base + (size_t)((c*2 + mt)*NK + ka)*A_STG, A_STG, mbFA + slot*8);
    };

    if (tid == 0){ issueB(); issueB(); issueB(); }

    const int rowA = wm*16 + (lane & 7) + (lane & 8);
    const int cbA  = lane >> 4;
    const int rowBl = lane & 7;
    const int cbB  = (lane >> 3) & 1;
    float* ghs = (float*)(smem + GHS_OFF);

    int sa = 0, pa = 0;       // A ring consumer state
    int sb = 0, pb = 0;       // B ring consumer state

    for (int p = 0; p <= NT; p++){
        for (int mt = 0; mt < nmt; mt++){
            if (tid == 0){ issueA(sa, p, mt, 0); issueA(sa ^ 1, p, mt, 1); }
            float acc[3][4];
            #pragma unroll
            for (int i = 0; i < 3; i++)
                #pragma unroll
                for (int j = 0; j < 4; j++) acc[i][j] = 0.f;

            for (int kt = 0; kt < NK; kt++){
                mbar_wait(mbFA + sa*8, pa);
                mbar_wait(mbFB + sb*8, pb);
                uint32_t sAb = smem_u32 + sa*A_STG;
                uint32_t sBb = smem_u32 + B_OFF + sb*B_STG;
                #pragma unroll
                for (int k16 = 0; k16 < KC/16; k16++){
                    int cb = k16*2;
                    uint32_t aaddr = sAb + rowA*128 + (((cb + cbA) ^ (rowA & 7)) << 4);
                    uint32_t a0,a1,a2,a3;
                    asm volatile("ldmatrix.sync.aligned.m8n8.x4.shared.b16 {%0,%1,%2,%3}, [%4];"
                                 : "=r"(a0),"=r"(a1),"=r"(a2),"=r"(a3) : "r"(aaddr));
                    #pragma unroll
                    for (int nt2 = 0; nt2 < 3; nt2++){
                        int rB = wn*24 + nt2*8 + rowBl;
                        uint32_t baddr = sBb + rB*128 + (((cb + cbB) ^ (rB & 7)) << 4);
                        uint32_t b0,b1;
                        asm volatile("ldmatrix.sync.aligned.m8n8.x2.shared.b16 {%0,%1}, [%2];"
                                     : "=r"(b0),"=r"(b1) : "r"(baddr));
                        asm volatile("mma.sync.aligned.m16n8k16.row.col.f32.f16.f16.f32 "
                                     "{%0,%1,%2,%3}, {%4,%5,%6,%7}, {%8,%9}, {%0,%1,%2,%3};"
                                     : "+f"(acc[nt2][0]),"+f"(acc[nt2][1]),"+f"(acc[nt2][2]),"+f"(acc[nt2][3])
                                     : "r"(a0),"r"(a1),"r"(a2),"r"(a3),"r"(b0),"r"(b1));
                    }
                }
                __syncthreads();
                if (tid == 0){
                    if (kt + 2 < NK) issueA(sa, p, mt, kt + 2);   // refill just-freed slot
                    issueB();                                      // continuous B stream
                }
                sa ^= 1; if (sa == 0) pa ^= 1;
                sb++;    if (sb == NSB){ sb = 0; pb ^= 1; }
            }

            // ---- fused epilogue in two 16-row rounds (ghs region, rings untouched) ----
            const int t = p - 1;
            const float* __restrict__ hc = (t & 1) ? g_hB : g_hA;
            float*       __restrict__ hn = (t & 1) ? g_hA : g_hB;
            char*        __restrict__ hPn = (t & 1) ? g_hPA : g_hPB;

            #pragma unroll
            for (int hh = 0; hh < 2; hh++){
                if (wm == hh){
                    int r0 = lane >> 2;
                    int colb = (lane & 3)*2;
                    #pragma unroll
                    for (int nt2 = 0; nt2 < 3; nt2++){
                        int ccol = wn*24 + nt2*8 + colb;
                        ghs[r0*104 + ccol]         = acc[nt2][0];
                        ghs[r0*104 + ccol + 1]     = acc[nt2][1];
                        ghs[(r0+8)*104 + ccol]     = acc[nt2][2];
                        ghs[(r0+8)*104 + ccol + 1] = acc[nt2][3];
                    }
                }
                __syncthreads();
                if (p == 0){
                    for (int idx = tid; idx < 16*24; idx += 256){
                        int ml = idx / 24, q = idx % 24;
                        int nl = q*4;
                        int mg = mt*TM + hh*16 + ml;
                        if (mg < bc){
                            int bidx = g_order[seg0 + mg];
                            int g = nl >> 5, jj = nl & 31;
                            int wrow = (g << 10) + j0 + jj;
                            float4 v = *(float4*)&ghs[ml*104 + nl];
                            float4 bi = __ldg((const float4*)(b_ih + (size_t)c*G3H + wrow));
                            v.x += bi.x; v.y += bi.y; v.z += bi.z; v.w += bi.w;
                            if (g < 2){
                                float4 bh = __ldg((const float4*)(b_hh + (size_t)c*G3H + wrow));
                                v.x += bh.x; v.y += bh.y; v.z += bh.z; v.w += bh.w;
                            }
                            *(float4*)(g_gi + (size_t)bidx*G3H + wrow) = v;
                        }
                    }
                } else if (tid < 128){
                    int ml = tid >> 3, jj = (tid & 7)*4;
                    int m = hh*16 + ml;
                    int mg = mt*TM + m;
                    if (mg < bc){
                        int bidx = g_order[seg0 + mg];
                        int j = j0 + jj;
                        float4 ghr  = *(float4*)&ghs[ml*104 + jj];
                        float4 ghz  = *(float4*)&ghs[ml*104 + 32 + jj];
                        float4 ghn4 = *(float4*)&ghs[ml*104 + 64 + jj];
                        const float* gi = g_gi + (size_t)bidx*G3H;
                        float4 gir = *(const float4*)(gi + j);
                        float4 giz = *(const float4*)(gi + H + j);
                        float4 gin = *(const float4*)(gi + 2*H + j);
                        float4 bn  = __ldg((const float4*)(b_hh + (size_t)c*G3H + 2*H + j));
                        float4 hold = *(const float4*)(hc + (size_t)bidx*H + j);
                        float4 hv;
                        {
                            float r0 = sigf(gir.x + ghr.x), z0 = sigf(giz.x + ghz.x);
                            float n0 = tanhfast(gin.x + r0*(ghn4.x + bn.x));
                            hv.x = (1.f - z0)*n0 + z0*hold.x;
                            float r1 = sigf(gir.y + ghr.y), z1 = sigf(giz.y + ghz.y);
                            float n1 = tanhfast(gin.y + r1*(ghn4.y + bn.y));
                            hv.y = (1.f - z1)*n1 + z1*hold.y;
                            float r2 = sigf(gir.z + ghr.z), z2 = sigf(giz.z + ghz.z);
                            float n2 = tanhfast(gin.z + r2*(ghn4.z + bn.z));
                            hv.z = (1.f - z2)*n2 + z2*hold.z;
                            float r3 = sigf(gir.w + ghr.w), z3 = sigf(giz.w + ghz.w);
                            float n3 = tanhfast(gin.w + r3*(ghn4.w + bn.w));
                            hv.w = (1.f - z3)*n3 + z3*hold.w;
                        }
                        *(float4*)(hn + (size_t)bidx*H + j) = hv;
                        __stcs((float4*)(g_hs + ((size_t)t*BATCH + bidx)*H + j), hv);
                        int kt2 = j >> 6, ch = (j >> 3) & 7, win = (j & 7)*2;
                        __half2 p0 = __floats2half2_rn(hv.x, hv.y);
                        __half2 p1 = __floats2half2_rn(hv.z, hv.w);
                        uint2 pk; pk.x = *(uint32_t*)&p0; pk.y = *(uint32_t*)&p1;
                        *(uint2*)(hPn + (size_t)((c*2+mt)*NK + kt2)*A_STG + m*128 + ((ch ^ (m&7))<<4) + win) = pk;
                    }
                }
                __syncthreads();
            }
        }
        // h(t) must be globally visible before step t+1 reads it via TMA
        if (p > 0 && p < NT) grid_barrier(tid);
    }
}

// ---------------- final transpose [T,B,H] -> [B,H,T] ----------------
__global__ void transpose_kernel(float* __restrict__ out){
    __shared__ float tile[NT*65];
    int b = blockIdx.y, j0 = blockIdx.x*64, tid = threadIdx.x;
    for (int idx = tid; idx < NT*64; idx += 256){
        int t = idx >> 6, jj = idx & 63;
        tile[t*65 + jj] = __ldcs(&g_hs[((size_t)t*BATCH + b)*H + j0 + jj]);
    }
    __syncthreads();
    for (int idx = tid; idx < NT*64; idx += 256){
        int jj = idx / NT, t = idx % NT;
        __stcs(&out[((size_t)b*H + j0 + jj)*NT + t], tile[t*65 + jj]);
    }
}

// ---------------- launch ----------------
extern "C" void kernel_launch(void* const* d_in, const int* in_sizes, int n_in,
                              void* d_out, int out_size)
{
    const float* x   = (const float*)d_in[0];
    const int*   cam = (const int*)  d_in[1];
    const float* Wih = (const float*)d_in[2];
    const float* Whh = (const float*)d_in[3];
    const float* bih = (const float*)d_in[4];
    const float* bhh = (const float*)d_in[5];
    float* out = (float*)d_out;

    cudaFuncSetAttribute(persistent_kernel, cudaFuncAttributeMaxDynamicSharedMemorySize, SMEM_DYN);

    setup_kernel<<<1, 256>>>(cam);
    init_pack_kernel<<<512, 256>>>(x);
    convert_pack_kernel<<<4096, 256>>>(Wih, Whh);

    persistent_kernel<<<dim3(32, NCAM), 256, SMEM_DYN>>>(bih, bhh);

    transpose_kernel<<<dim3(16, BATCH), 256>>>(out);
}

// round 15
// speedup vs baseline: 1.0173x; 1.0173x over previous
#include <cuda_runtime.h>
#include <cuda_fp16.h>
#include <math.h>
#include <stdint.h>

#define H     1024
#define BATCH 256
#define NCAM  15
#define NT    60
#define G3H   3072

#define TM 32
#define TJ 32
#define TN 96
#define KC 64
#define NK (H/KC)
#define NSTG 3
#define A_STG 4096
#define B_STG 12288
#define B_HALF 6144
#define STAGE_BYTES (A_STG + B_STG)       // 16KB
#define SMEM_MAIN (NSTG*STAGE_BYTES)
#define SMEM_DYN  (SMEM_MAIN + 64)
#define MAXMT 24

// ---------------- scratch (static device globals) ----------------
__device__ __align__(128) char g_Pwhh[(size_t)NCAM*32*NK*B_STG];
__device__ __align__(128) char g_hPA [(size_t)NCAM*2*NK*A_STG];
__device__ __align__(128) char g_hPB [(size_t)NCAM*2*NK*A_STG];
__device__ __align__(128) float g_hA[BATCH*H];
__device__ __align__(128) float g_hB[BATCH*H];
__device__ __align__(128) float g_gi[(size_t)BATCH*G3H];   // gi + b_ih + b_hh(r,z)
__device__ __align__(128) float g_hs[(size_t)NT*BATCH*H];
__device__ int g_order[BATCH];
__device__ int g_seg[NCAM+1];
__device__ int g_mtile[MAXMT];
__device__ int g_nmt;

// ---------------- ptx helpers ----------------
__device__ __forceinline__ void mbar_init(uint32_t a, uint32_t cnt){
    asm volatile("mbarrier.init.shared.b64 [%0], %1;" :: "r"(a), "r"(cnt) : "memory");
}
__device__ __forceinline__ void mbar_expect(uint32_t a, uint32_t tx){
    asm volatile("mbarrier.arrive.expect_tx.shared.b64 _, [%0], %1;" :: "r"(a), "r"(tx) : "memory");
}
__device__ __forceinline__ void mbar_arrive(uint32_t a){
    asm volatile("mbarrier.arrive.shared.b64 _, [%0];" :: "r"(a) : "memory");
}
__device__ __forceinline__ void mbar_arrive_peer(uint32_t a, uint32_t rank){
    asm volatile("{\n\t.reg .b32 ra;\n\t"
                 "mapa.shared::cluster.u32 ra, %0, %1;\n\t"
                 "mbarrier.arrive.shared::cluster.b64 _, [ra];\n\t}"
                 :: "r"(a), "r"(rank) : "memory");
}
__device__ __forceinline__ void bulk_g2s(uint32_t dst, const void* src, uint32_t bytes, uint32_t mbar){
    asm volatile("cp.async.bulk.shared::cta.global.mbarrier::complete_tx::bytes [%0], [%1], %2, [%3];"
                 :: "r"(dst), "l"(src), "r"(bytes), "r"(mbar) : "memory");
}
__device__ __forceinline__ void bulk_g2s_mc(uint32_t dst, const void* src, uint32_t bytes,
                                            uint32_t mbar, uint16_t mask){
    asm volatile("cp.async.bulk.shared::cluster.global.mbarrier::complete_tx::bytes.multicast::cluster "
                 "[%0], [%1], %2, [%3], %4;"
                 :: "r"(dst), "l"(src), "r"(bytes), "r"(mbar), "h"(mask) : "memory");
}
__device__ __forceinline__ void mbar_wait(uint32_t a, uint32_t phase){
    asm volatile("{\n\t.reg .pred P;\n\t"
                 "WL_%=:\n\t"
                 "mbarrier.try_wait.parity.acquire.cta.shared::cta.b64 P, [%0], %1, 0x989680;\n\t"
                 "@P bra.uni WD_%=;\n\t"
                 "bra.uni WL_%=;\n\t"
                 "WD_%=:\n\t}"
                 :: "r"(a), "r"(phase) : "memory");
}
#define CLUSTER_SYNC() do { \
    asm volatile("barrier.cluster.arrive.aligned;" ::: "memory"); \
    asm volatile("barrier.cluster.wait.aligned;" ::: "memory"); \
} while(0)
__device__ __forceinline__ float sigf(float x){ return 1.f/(1.f + __expf(-x)); }
__device__ __forceinline__ float tanhfast(float x){ return 2.f/(1.f + __expf(-2.f*x)) - 1.f; }

// ---------------- setup: group by camera + pairs-first mtile table ----------------
__global__ void setup_kernel(const int* __restrict__ cam){
    __shared__ int cnt[NCAM], offs[NCAM];
    int tid = threadIdx.x;
    if (tid < NCAM) cnt[tid] = 0;
    __syncthreads();
    int c = cam[tid];
    atomicAdd(&cnt[c], 1);
    __syncthreads();
    if (tid == 0){
        int s = 0;
        for (int i = 0; i < NCAM; i++){ offs[i] = s; g_seg[i] = s; s += cnt[i]; }
        g_seg[NCAM] = s;
        int nm = 0;
        for (int i = 0; i < NCAM; i++){
            if (cnt[i] > TM && nm + 1 < MAXMT){
                g_mtile[nm++] = (i << 1) | 0;
                g_mtile[nm++] = (i << 1) | 1;
            }
        }
        for (int i = 0; i < NCAM; i++){
            if (cnt[i] > 0 && cnt[i] <= TM && nm < MAXMT)
                g_mtile[nm++] = (i << 1) | 0;
        }
        g_nmt = nm;
        for (int k = nm; k < MAXMT; k++) g_mtile[k] = -1;
    }
    __syncthreads();
    int p = atomicAdd(&offs[c], 1);
    g_order[p] = tid;
}

// ---------------- init: zero hP ping-pong buffers and hA ----------------
#define HPCH  (NCAM*2*NK*256)
__global__ void init_kernel(){
    const int total = 2*HPCH + BATCH*H/4;
    int stride = gridDim.x*blockDim.x;
    for (int i = blockIdx.x*blockDim.x + threadIdx.x; i < total; i += stride){
        if (i < 2*HPCH){
            if (i < HPCH) ((uint4*)g_hPA)[i] = make_uint4(0,0,0,0);
            else          ((uint4*)g_hPB)[i-HPCH] = make_uint4(0,0,0,0);
        } else {
            int k = i - 2*HPCH;
            ((float4*)g_hA)[k] = make_float4(0.f,0.f,0.f,0.f);
        }
    }
}

// ---------------- convert + pack W_hh only: fp32 -> fp16 swizzled tiles ----------------
__global__ void convert_pack_kernel(const float* __restrict__ wh){
    const size_t NCH = (size_t)NCAM*32*NK*768;
    size_t stride = (size_t)gridDim.x*blockDim.x;
    for (size_t i = (size_t)blockIdx.x*blockDim.x + threadIdx.x; i < NCH; i += stride){
        size_t blk = i / 768; int cin = (int)(i % 768);
        int r = cin >> 3, ch = cin & 7;
        int kt = (int)(blk & 15); size_t cj = blk >> 4;
        int jt = (int)(cj & 31); int c = (int)(cj >> 5);
        int grow = ((r>>5)<<10) + jt*TJ + (r & 31);
        size_t src = (((size_t)c*G3H + grow)<<10) + kt*KC + ch*8;
        size_t dst = blk*B_STG + r*128 + ((ch ^ (r&7))<<4);
        const float4* s = (const float4*)(wh + src);
        float4 a = __ldcs(s), b = __ldcs(s+1);
        __half2 h0 = __floats2half2_rn(a.x,a.y), h1 = __floats2half2_rn(a.z,a.w);
        __half2 h2 = __floats2half2_rn(b.x,b.y), h3 = __floats2half2_rn(b.z,b.w);
        uint4 v; v.x=*(uint32_t*)&h0; v.y=*(uint32_t*)&h1; v.z=*(uint32_t*)&h2; v.w=*(uint32_t*)&h3;
        *(uint4*)(g_Pwhh + dst) = v;
    }
}

// ---------------- gi kernel: fp32 GEMM, gi = x @ Wih^T + b_ih + b_hh(r,z) ----------------
// grid (NCAM, 24): camera c, 128-weight-row chunk. M<=64 samples, N=128, K=1024.
#define GI_KB 16
__global__ void __launch_bounds__(256) gi_kernel(const float* __restrict__ x,
                                                 const float* __restrict__ wi,
                                                 const float* __restrict__ b_ih,
                                                 const float* __restrict__ b_hh)
{
    __shared__ float xs[64][GI_KB+1];
    __shared__ float ws[128][GI_KB+2];
    const int c = blockIdx.x, chunk = blockIdx.y;
    const int seg0 = g_seg[c], bc = g_seg[c+1] - seg0;
    if (bc == 0) return;
    const int tid = threadIdx.x;
    const int ty = tid >> 4, tx = tid & 15;       // 16x16

    for (int m0 = 0; m0 < bc; m0 += 64){
        float acc[4][8];
        #pragma unroll
        for (int i = 0; i < 4; i++)
            #pragma unroll
            for (int j = 0; j < 8; j++) acc[i][j] = 0.f;

        for (int k0 = 0; k0 < H; k0 += GI_KB){
            // load x tile: 64 x 16 (m = tid/4, kk = (tid%4)*4)
            {
                int m = tid >> 2, kk = (tid & 3)*4;
                float4 v = make_float4(0.f,0.f,0.f,0.f);
                int mg = m0 + m;
                if (mg < bc){
                    int bidx = g_order[seg0 + mg];
                    v = *(const float4*)(x + (size_t)bidx*H + k0 + kk);
                }
                xs[m][kk] = v.x; xs[m][kk+1] = v.y; xs[m][kk+2] = v.z; xs[m][kk+3] = v.w;
            }
            // load W tile: 128 x 16 (n = tid/2, kk = (tid%2)*8)
            {
                int n = tid >> 1, kk = (tid & 1)*8;
                const float4* s = (const float4*)(wi + (((size_t)c*G3H + chunk*128 + n)<<10) + k0 + kk);
                float4 a = __ldcs(s), b = __ldcs(s+1);
                ws[n][kk]   = a.x; ws[n][kk+1] = a.y; ws[n][kk+2] = a.z; ws[n][kk+3] = a.w;
                ws[n][kk+4] = b.x; ws[n][kk+5] = b.y; ws[n][kk+6] = b.z; ws[n][kk+7] = b.w;
            }
            __syncthreads();
            #pragma unroll
            for (int k = 0; k < GI_KB; k++){
                float xv[4], wv[8];
                #pragma unroll
                for (int i = 0; i < 4; i++) xv[i] = xs[ty*4 + i][k];
                #pragma unroll
                for (int j = 0; j < 8; j++) wv[j] = ws[tx*8 + j][k];
                #pragma unroll
                for (int i = 0; i < 4; i++)
                    #pragma unroll
                    for (int j = 0; j < 8; j++) acc[i][j] += xv[i]*wv[j];
            }
            __syncthreads();
        }
        // store with biases folded
        #pragma unroll
        for (int i = 0; i < 4; i++){
            int mg = m0 + ty*4 + i;
            if (mg < bc){
                int bidx = g_order[seg0 + mg];
                #pragma unroll
                for (int j = 0; j < 8; j++){
                    int wrow = chunk*128 + tx*8 + j;
                    float v = acc[i][j] + __ldg(&b_ih[(size_t)c*G3H + wrow]);
                    if (wrow < 2*H) v += __ldg(&b_hh[(size_t)c*G3H + wrow]);
                    g_gi[(size_t)bidx*G3H + wrow] = v;
                }
            }
        }
        __syncthreads();
    }
}

// ---------------- clustered bulk-fed GEMM step + fused GRU epilogue (R8 verbatim) ----------------
__global__ void __launch_bounds__(256, 4) __cluster_dims__(1, 2, 1)
gemm_step_kernel(const float* __restrict__ b_hh, int t)
{
    extern __shared__ __align__(128) char smem[];
    const int jt = blockIdx.x;
    const int y  = blockIdx.y;
    const int rank = y & 1;
    const int cm  = g_mtile[y];
    const int cmp = g_mtile[y ^ 1];
    const bool active = (cm >= 0);
    const bool paired = active && (cmp >= 0) && ((cm >> 1) == (cmp >> 1));

    const int tid  = threadIdx.x;
    uint32_t smem_u32 = (uint32_t)__cvta_generic_to_shared(smem);
    uint32_t mbF = smem_u32 + SMEM_MAIN;
    uint32_t mbE = mbF + 24;

    if (tid == 0){
        uint32_t ecnt = paired ? 2u : 1u;
        #pragma unroll
        for (int s = 0; s < NSTG; s++){ mbar_init(mbF + s*8, 1); mbar_init(mbE + s*8, ecnt); }
        asm volatile("fence.proxy.async.shared::cta;" ::: "memory");
    }
    __syncthreads();
    CLUSTER_SYNC();

    if (active){
        const int c  = cm >> 1;
        const int mt = cm & 1;
        const int seg0 = g_seg[c];
        const int bc   = g_seg[c+1] - seg0;

        const char* __restrict__ Apack = (t & 1) ? g_hPB : g_hPA;
        const char* Asrc = Apack + (size_t)((c*2+mt)*NK)*A_STG;
        const char* Bsrc = g_Pwhh + (size_t)((c*32+jt)*NK)*B_STG;

        const int j0   = jt*TJ;
        const int lane = tid & 31, warp = tid >> 5;
        const int wm = warp & 1, wn = warp >> 1;

        auto issue = [&](int kt){
            if (kt < NK){
                int s = kt % NSTG, q = kt / NSTG;
                if (q >= 1) mbar_wait(mbE + s*8, (q-1) & 1);
                uint32_t stg = smem_u32 + s*STAGE_BYTES;
                mbar_expect(mbF + s*8, STAGE_BYTES);
                bulk_g2s(stg, Asrc + (size_t)kt*A_STG, A_STG, mbF + s*8);
                if (paired){
                    bulk_g2s_mc(stg + A_STG + rank*B_HALF,
                                Bsrc + (size_t)kt*B_STG + rank*B_HALF,
                                B_HALF, mbF + s*8, 0x3);
                } else {
                    bulk_g2s(stg + A_STG, Bsrc + (size_t)kt*B_STG, B_STG, mbF + s*8);
                }
            }
        };
        if (tid == 0){ issue(0); issue(1); issue(2); }

        float acc[3][4];
        #pragma unroll
        for (int i = 0; i < 3; i++)
            #pragma unroll
            for (int j = 0; j < 4; j++) acc[i][j] = 0.f;

        const int rowA = wm*16 + (lane & 7) + (lane & 8);
        const int cbA  = lane >> 4;
        const int rowBl = lane & 7;
        const int cbB  = (lane >> 3) & 1;

        for (int kt = 0; kt < NK; kt++){
            int s = kt % NSTG;
            mbar_wait(mbF + s*8, (kt/NSTG) & 1);
            uint32_t sA = smem_u32 + s*STAGE_BYTES;
            uint32_t sB = sA + A_STG;
            #pragma unroll
            for (int k16 = 0; k16 < KC/16; k16++){
                int cb = k16*2;
                uint32_t aaddr = sA + rowA*128 + (((cb + cbA) ^ (rowA & 7)) << 4);
                uint32_t a0,a1,a2,a3;
                asm volatile("ldmatrix.sync.aligned.m8n8.x4.shared.b16 {%0,%1,%2,%3}, [%4];"
                             : "=r"(a0),"=r"(a1),"=r"(a2),"=r"(a3) : "r"(aaddr));
                #pragma unroll
                for (int nt = 0; nt < 3; nt++){
                    int rB = wn*24 + nt*8 + rowBl;
                    uint32_t baddr = sB + rB*128 + (((cb + cbB) ^ (rB & 7)) << 4);
                    uint32_t b0,b1;
                    asm volatile("ldmatrix.sync.aligned.m8n8.x2.shared.b16 {%0,%1}, [%2];"
                                 : "=r"(b0),"=r"(b1) : "r"(baddr));
                    asm volatile("mma.sync.aligned.m16n8k16.row.col.f32.f16.f16.f32 "
                                 "{%0,%1,%2,%3}, {%4,%5,%6,%7}, {%8,%9}, {%0,%1,%2,%3};"
                                 : "+f"(acc[nt][0]),"+f"(acc[nt][1]),"+f"(acc[nt][2]),"+f"(acc[nt][3])
                                 : "r"(a0),"r"(a1),"r"(a2),"r"(a3),"r"(b0),"r"(b1));
                }
            }
            __syncthreads();
            if (tid == 0){
                mbar_arrive(mbE + s*8);
                if (paired) mbar_arrive_peer(mbE + s*8, rank ^ 1);
                issue(kt + NSTG);
            }
        }

        float* ghs = (float*)smem;
        {
            int r0 = wm*16 + (lane >> 2);
            int colb = (lane & 3)*2;
            #pragma unroll
            for (int nt = 0; nt < 3; nt++){
                int ccol = wn*24 + nt*8 + colb;
                ghs[r0*104 + ccol]         = acc[nt][0];
                ghs[r0*104 + ccol + 1]     = acc[nt][1];
                ghs[(r0+8)*104 + ccol]     = acc[nt][2];
                ghs[(r0+8)*104 + ccol + 1] = acc[nt][3];
            }
        }
        __syncthreads();

        {
            const float* __restrict__ hc = (t & 1) ? g_hB : g_hA;
            float*       __restrict__ hn = (t & 1) ? g_hA : g_hB;
            char*        __restrict__ hPn = (t & 1) ? g_hPA : g_hPB;
            int m = tid >> 3, jj = (tid & 7)*4;
            int mg = mt*TM + m;
            if (mg < bc){
                int bidx = g_order[seg0 + mg];
                int j = j0 + jj;
                float4 ghr = *(float4*)&ghs[m*104 + jj];
                float4 ghz = *(float4*)&ghs[m*104 + 32 + jj];
                float4 ghn4 = *(float4*)&ghs[m*104 + 64 + jj];
                const float* gi = g_gi + (size_t)bidx*G3H;
                float4 gir = *(const float4*)(gi + j);
                float4 giz = *(const float4*)(gi + H + j);
                float4 gin = *(const float4*)(gi + 2*H + j);
                float4 bn  = __ldg((const float4*)(b_hh + (size_t)c*G3H + 2*H + j));
                float4 hold = *(const float4*)(hc + (size_t)bidx*H + j);
                float4 hv;
                {
                    float r0 = sigf(gir.x + ghr.x), z0 = sigf(giz.x + ghz.x);
                    float n0 = tanhfast(gin.x + r0*(ghn4.x + bn.x));
                    hv.x = (1.f - z0)*n0 + z0*hold.x;
                    float r1 = sigf(gir.y + ghr.y), z1 = sigf(giz.y + ghz.y);
                    float n1 = tanhfast(gin.y + r1*(ghn4.y + bn.y));
                    hv.y = (1.f - z1)*n1 + z1*hold.y;
                    float r2 = sigf(gir.z + ghr.z), z2 = sigf(giz.z + ghz.z);
                    float n2 = tanhfast(gin.z + r2*(ghn4.z + bn.z));
                    hv.z = (1.f - z2)*n2 + z2*hold.z;
                    float r3 = sigf(gir.w + ghr.w), z3 = sigf(giz.w + ghz.w);
                    float n3 = tanhfast(gin.w + r3*(ghn4.w + bn.w));
                    hv.w = (1.f - z3)*n3 + z3*hold.w;
                }
                *(float4*)(hn + (size_t)bidx*H + j) = hv;
                __stcs((float4*)(g_hs + ((size_t)t*BATCH + bidx)*H + j), hv);
                int kt = j >> 6, ch = (j >> 3) & 7, win = (j & 7)*2;
                __half2 p0 = __floats2half2_rn(hv.x, hv.y);
                __half2 p1 = __floats2half2_rn(hv.z, hv.w);
                uint2 pk; pk.x = *(uint32_t*)&p0; pk.y = *(uint32_t*)&p1;
                *(uint2*)(hPn + (size_t)((c*2+mt)*NK + kt)*A_STG + m*128 + ((ch ^ (m&7))<<4) + win) = pk;
            }
        }
    }

    CLUSTER_SYNC();
}

// ---------------- final transpose [T,B,H] -> [B,H,T] ----------------
__global__ void transpose_kernel(float* __restrict__ out){
    __shared__ float tile[NT*65];
    int b = blockIdx.y, j0 = blockIdx.x*64, tid = threadIdx.x;
    for (int idx = tid; idx < NT*64; idx += 256){
        int t = idx >> 6, jj = idx & 63;
        tile[t*65 + jj] = __ldcs(&g_hs[((size_t)t*BATCH + b)*H + j0 + jj]);
    }
    __syncthreads();
    for (int idx = tid; idx < NT*64; idx += 256){
        int jj = idx / NT, t = idx % NT;
        __stcs(&out[((size_t)b*H + j0 + jj)*NT + t], tile[t*65 + jj]);
    }
}

// ---------------- launch ----------------
extern "C" void kernel_launch(void* const* d_in, const int* in_sizes, int n_in,
                              void* d_out, int out_size)
{
    const float* x   = (const float*)d_in[0];
    const int*   cam = (const int*)  d_in[1];
    const float* Wih = (const float*)d_in[2];
    const float* Whh = (const float*)d_in[3];
    const float* bih = (const float*)d_in[4];
    const float* bhh = (const float*)d_in[5];
    float* out = (float*)d_out;

    cudaFuncSetAttribute(gemm_step_kernel, cudaFuncAttributeMaxDynamicSharedMemorySize, SMEM_DYN);

    setup_kernel<<<1, 256>>>(cam);
    init_kernel<<<512, 256>>>();
    convert_pack_kernel<<<2048, 256>>>(Whh);
    gi_kernel<<<dim3(NCAM, 24), 256>>>(x, Wih, bih, bhh);

    dim3 grid(32, MAXMT);
    for (int t = 0; t < NT; t++)
        gemm_step_kernel<<<grid, 256, SMEM_DYN>>>(bhh, t);

    transpose_kernel<<<dim3(16, BATCH), 256>>>(out);
}

// round 16
// speedup vs baseline: 1.4722x; 1.4471x over previous
#include <cuda_runtime.h>
#include <cuda_fp16.h>
#include <math.h>
#include <stdint.h>

#define H     1024
#define BATCH 256
#define NCAM  15
#define NT    60
#define G3H   3072

#define TM 32
#define TJ 32
#define TN 96
#define KC 64
#define NK (H/KC)
#define NSTG 3
#define A_STG 4096
#define B_STG 12288
#define B_HALF 6144
#define STAGE_BYTES (A_STG + B_STG)       // 16KB
#define SMEM_MAIN (NSTG*STAGE_BYTES)
#define SMEM_DYN  (SMEM_MAIN + 64)
#define MAXMT 24

// convert kernel staging
#define CV_FP32_STG 24576                 // 96 rows x 256B fp32
#define CV_SMEM (2*CV_FP32_STG + 2*B_STG + 32)   // 73760
#define CV_GRID 1920
#define CV_TILES (2*NCAM*32*16)           // 15360, 8 per CTA

// ---------------- scratch (static device globals) ----------------
__device__ __align__(128) char g_Pwih[(size_t)NCAM*32*NK*B_STG];
__device__ __align__(128) char g_Pwhh[(size_t)NCAM*32*NK*B_STG];
__device__ __align__(128) char g_xpack[(size_t)NCAM*2*NK*A_STG];
__device__ __align__(128) char g_hPA [(size_t)NCAM*2*NK*A_STG];
__device__ __align__(128) char g_hPB [(size_t)NCAM*2*NK*A_STG];
__device__ __align__(128) float g_hA[BATCH*H];
__device__ __align__(128) float g_hB[BATCH*H];
__device__ __align__(128) float g_gi[(size_t)BATCH*G3H];   // gi + b_ih + b_hh(r,z)
__device__ __align__(128) float g_hs[(size_t)NT*BATCH*H];
__device__ int g_order[BATCH];
__device__ int g_seg[NCAM+1];
__device__ int g_mtile[MAXMT];    // packed (c<<1)|mt; pairs-first ordering
__device__ int g_nmt;

// ---------------- ptx helpers ----------------
__device__ __forceinline__ void mbar_init(uint32_t a, uint32_t cnt){
    asm volatile("mbarrier.init.shared.b64 [%0], %1;" :: "r"(a), "r"(cnt) : "memory");
}
__device__ __forceinline__ void mbar_expect(uint32_t a, uint32_t tx){
    asm volatile("mbarrier.arrive.expect_tx.shared.b64 _, [%0], %1;" :: "r"(a), "r"(tx) : "memory");
}
__device__ __forceinline__ void mbar_arrive(uint32_t a){
    asm volatile("mbarrier.arrive.shared.b64 _, [%0];" :: "r"(a) : "memory");
}
__device__ __forceinline__ void mbar_arrive_peer(uint32_t a, uint32_t rank){
    asm volatile("{\n\t.reg .b32 ra;\n\t"
                 "mapa.shared::cluster.u32 ra, %0, %1;\n\t"
                 "mbarrier.arrive.shared::cluster.b64 _, [ra];\n\t}"
                 :: "r"(a), "r"(rank) : "memory");
}
__device__ __forceinline__ void bulk_g2s(uint32_t dst, const void* src, uint32_t bytes, uint32_t mbar){
    asm volatile("cp.async.bulk.shared::cta.global.mbarrier::complete_tx::bytes [%0], [%1], %2, [%3];"
                 :: "r"(dst), "l"(src), "r"(bytes), "r"(mbar) : "memory");
}
__device__ __forceinline__ void bulk_g2s_mc(uint32_t dst, const void* src, uint32_t bytes,
                                            uint32_t mbar, uint16_t mask){
    asm volatile("cp.async.bulk.shared::cluster.global.mbarrier::complete_tx::bytes.multicast::cluster "
                 "[%0], [%1], %2, [%3], %4;"
                 :: "r"(dst), "l"(src), "r"(bytes), "r"(mbar), "h"(mask) : "memory");
}
__device__ __forceinline__ void bulk_s2g(void* dst, uint32_t src, uint32_t bytes){
    asm volatile("cp.async.bulk.global.shared::cta.bulk_group [%0], [%1], %2;"
                 :: "l"(dst), "r"(src), "r"(bytes) : "memory");
}
__device__ __forceinline__ void mbar_wait(uint32_t a, uint32_t phase){
    asm volatile("{\n\t.reg .pred P;\n\t"
                 "WL_%=:\n\t"
                 "mbarrier.try_wait.parity.acquire.cta.shared::cta.b64 P, [%0], %1, 0x989680;\n\t"
                 "@P bra.uni WD_%=;\n\t"
                 "bra.uni WL_%=;\n\t"
                 "WD_%=:\n\t}"
                 :: "r"(a), "r"(phase) : "memory");
}
#define CLUSTER_SYNC() do { \
    asm volatile("barrier.cluster.arrive.aligned;" ::: "memory"); \
    asm volatile("barrier.cluster.wait.aligned;" ::: "memory"); \
} while(0)
__device__ __forceinline__ float sigf(float x){ return 1.f/(1.f + __expf(-x)); }
__device__ __forceinline__ float tanhfast(float x){ return 2.f/(1.f + __expf(-2.f*x)) - 1.f; }

// ---------------- setup: group by camera + pairs-first mtile table ----------------
__global__ void setup_kernel(const int* __restrict__ cam){
    __shared__ int cnt[NCAM], offs[NCAM];
    int tid = threadIdx.x;
    if (tid < NCAM) cnt[tid] = 0;
    __syncthreads();
    int c = cam[tid];
    atomicAdd(&cnt[c], 1);
    __syncthreads();
    if (tid == 0){
        int s = 0;
        for (int i = 0; i < NCAM; i++){ offs[i] = s; g_seg[i] = s; s += cnt[i]; }
        g_seg[NCAM] = s;
        int nm = 0;
        for (int i = 0; i < NCAM; i++){
            if (cnt[i] > TM && nm + 1 < MAXMT){
                g_mtile[nm++] = (i << 1) | 0;
                g_mtile[nm++] = (i << 1) | 1;
            }
        }
        for (int i = 0; i < NCAM; i++){
            if (cnt[i] > 0 && cnt[i] <= TM && nm < MAXMT)
                g_mtile[nm++] = (i << 1) | 0;
        }
        g_nmt = nm;
        for (int k = nm; k < MAXMT; k++) g_mtile[k] = -1;
    }
    __syncthreads();
    int p = atomicAdd(&offs[c], 1);
    g_order[p] = tid;
}

// ---------------- init: pack x (sorted+swizzled), zero hP/hA ----------------
#define XCH   (NCAM*2*NK*256)
#define HPCH  (NCAM*2*NK*256)
__global__ void init_pack_kernel(const float* __restrict__ x){
    const int total = XCH + 2*HPCH + BATCH*H/4;
    int stride = gridDim.x*blockDim.x;
    for (int i = blockIdx.x*blockDim.x + threadIdx.x; i < total; i += stride){
        if (i < XCH){
            int blk = i >> 8, cin = i & 255;
            int r = cin >> 3, ch = cin & 7;
            int kt = blk & 15, cm = blk >> 4;
            int mt = cm & 1, c = cm >> 1;
            int seg0 = g_seg[c], bc = g_seg[c+1]-seg0;
            int mg = mt*TM + r;
            uint4 v = make_uint4(0,0,0,0);
            if (mg < bc){
                int bidx = g_order[seg0+mg];
                const float4* s = (const float4*)(x + (size_t)bidx*H + kt*KC + ch*8);
                float4 a = s[0], b = s[1];
                __half2 h0 = __floats2half2_rn(a.x,a.y), h1 = __floats2half2_rn(a.z,a.w);
                __half2 h2 = __floats2half2_rn(b.x,b.y), h3 = __floats2half2_rn(b.z,b.w);
                v.x = *(uint32_t*)&h0; v.y = *(uint32_t*)&h1;
                v.z = *(uint32_t*)&h2; v.w = *(uint32_t*)&h3;
            }
            *(uint4*)(g_xpack + (size_t)blk*A_STG + r*128 + ((ch ^ (r&7))<<4)) = v;
        } else if (i < XCH + 2*HPCH){
            int k = i - XCH;
            if (k < HPCH) ((uint4*)g_hPA)[k] = make_uint4(0,0,0,0);
            else          ((uint4*)g_hPB)[k-HPCH] = make_uint4(0,0,0,0);
        } else {
            int k = i - XCH - 2*HPCH;
            ((float4*)g_hA)[k] = make_float4(0.f,0.f,0.f,0.f);
        }
    }
}

// ---------------- TMA-fed convert: fp32 weights -> packed swizzled fp16 tiles ----------------
// tile id = (((c*32+jt)*16+kt)*2 + tsel). Per tile: 96 x 256B bulk gathers -> fp32 stage,
// register convert + swizzled STS -> fp16 stage, one 12KB bulk store. Double-buffered.
__global__ void __launch_bounds__(256) convert_pack_kernel(const float* __restrict__ wi,
                                                           const float* __restrict__ wh){
    extern __shared__ __align__(128) char cs[];
    uint32_t sb = (uint32_t)__cvta_generic_to_shared(cs);
    const uint32_t fp32s = sb;                      // 2 x 24576
    const uint32_t fp16s = sb + 2*CV_FP32_STG;      // 2 x 12288
    const uint32_t mb    = sb + 2*CV_FP32_STG + 2*B_STG;
    const int tid = threadIdx.x;

    if (tid == 0){
        mbar_init(mb, 1); mbar_init(mb + 8, 1);
        asm volatile("fence.proxy.async.shared::cta;" ::: "memory");
    }
    __syncthreads();

    const int t0 = blockIdx.x * 8;                  // CV_GRID*8 == CV_TILES
    const int n  = 8;

    auto issue = [&](int i){                        // tid0 only
        int tile = t0 + i;
        int tsel = tile & 1;
        int q = (tile >> 1) & 511;
        int kt = q & 15, jt = q >> 4;
        int c  = tile >> 10;
        const float* W = tsel ? wh : wi;
        int b = i & 1;
        mbar_expect(mb + b*8, CV_FP32_STG);
        uint32_t dstb = fp32s + b*CV_FP32_STG;
        const float* base = W + ((size_t)c*G3H << 10) + kt*KC;
        #pragma unroll 4
        for (int r = 0; r < 96; r++){
            int grow = ((r >> 5) << 10) + jt*TJ + (r & 31);
            bulk_g2s(dstb + r*256, base + ((size_t)grow << 10), 256, mb + b*8);
        }
    };
    if (tid == 0) issue(0);

    for (int i = 0; i < n; i++){
        int b = i & 1;
        if (tid == 0 && i + 1 < n) issue(i + 1);
        mbar_wait(mb + b*8, (i >> 1) & 1);
        // fp16 buf b's previous bulk store (tile i-2) must be done before overwrite
        if (tid == 0) asm volatile("cp.async.bulk.wait_group 1;" ::: "memory");
        __syncthreads();
        // convert 96x64 fp32 -> swizzled fp16 tile
        uint32_t srcb = fp32s + b*CV_FP32_STG;
        uint32_t outb = fp16s + b*B_STG;
        #pragma unroll
        for (int qq = 0; qq < 3; qq++){
            int idx = tid + qq*256;                 // 768 16B-chunks
            int r = idx >> 3, ch = idx & 7;
            uint32_t sa = srcb + r*256 + ch*32;
            float4 a, bb;
            asm volatile("ld.shared.v4.f32 {%0,%1,%2,%3}, [%4];"
                         : "=f"(a.x),"=f"(a.y),"=f"(a.z),"=f"(a.w) : "r"(sa));
            asm volatile("ld.shared.v4.f32 {%0,%1,%2,%3}, [%4];"
                         : "=f"(bb.x),"=f"(bb.y),"=f"(bb.z),"=f"(bb.w) : "r"(sa + 16));
            __half2 h0 = __floats2half2_rn(a.x,a.y),  h1 = __floats2half2_rn(a.z,a.w);
            __half2 h2 = __floats2half2_rn(bb.x,bb.y), h3 = __floats2half2_rn(bb.z,bb.w);
            uint32_t da = outb + r*128 + ((ch ^ (r & 7)) << 4);
            asm volatile("st.shared.v4.b32 [%0], {%1,%2,%3,%4};"
                         :: "r"(da), "r"(*(uint32_t*)&h0), "r"(*(uint32_t*)&h1),
                            "r"(*(uint32_t*)&h2), "r"(*(uint32_t*)&h3) : "memory");
        }
        __syncthreads();
        if (tid == 0){
            int tile = t0 + i;
            int tsel = tile & 1;
            int q = (tile >> 1) & 511;
            int kt = q & 15, jt = q >> 4;
            int c  = tile >> 10;
            char* dst = (tsel ? g_Pwhh : g_Pwih) + (size_t)(((c*32 + jt) << 4) + kt) * B_STG;
            asm volatile("fence.proxy.async.shared::cta;" ::: "memory");
            bulk_s2g(dst, outb, B_STG);
            asm volatile("cp.async.bulk.commit_group;" ::: "memory");
        }
    }
    if (tid == 0) asm volatile("cp.async.bulk.wait_group 0;" ::: "memory");
}

// ---------------- clustered bulk-fed GEMM + fused GRU epilogue (R8 verbatim) ----------------
template<int MODE>
__global__ void __launch_bounds__(256, 4) __cluster_dims__(1, 2, 1)
gemm_step_kernel(const float* __restrict__ b_ih, const float* __restrict__ b_hh, int t)
{
    extern __shared__ __align__(128) char smem[];
    const int jt = blockIdx.x;
    const int y  = blockIdx.y;
    const int rank = y & 1;
    const int cm  = g_mtile[y];
    const int cmp = g_mtile[y ^ 1];
    const bool active = (cm >= 0);
    const bool paired = active && (cmp >= 0) && ((cm >> 1) == (cmp >> 1));

    const int tid  = threadIdx.x;
    uint32_t smem_u32 = (uint32_t)__cvta_generic_to_shared(smem);
    uint32_t mbF = smem_u32 + SMEM_MAIN;
    uint32_t mbE = mbF + 24;

    if (tid == 0){
        uint32_t ecnt = paired ? 2u : 1u;
        #pragma unroll
        for (int s = 0; s < NSTG; s++){ mbar_init(mbF + s*8, 1); mbar_init(mbE + s*8, ecnt); }
        asm volatile("fence.proxy.async.shared::cta;" ::: "memory");
    }
    __syncthreads();
    CLUSTER_SYNC();

    if (active){
        const int c  = cm >> 1;
        const int mt = cm & 1;
        const int seg0 = g_seg[c];
        const int bc   = g_seg[c+1] - seg0;

        const char* __restrict__ Apack = (MODE==0) ? g_xpack : ((t & 1) ? g_hPB : g_hPA);
        const char* __restrict__ Bpack = (MODE==0) ? g_Pwih : g_Pwhh;
        const char* Asrc = Apack + (size_t)((c*2+mt)*NK)*A_STG;
        const char* Bsrc = Bpack + (size_t)((c*32+jt)*NK)*B_STG;

        const int j0   = jt*TJ;
        const int lane = tid & 31, warp = tid >> 5;
        const int wm = warp & 1, wn = warp >> 1;

        auto issue = [&](int kt){
            if (kt < NK){
                int s = kt % NSTG, q = kt / NSTG;
                if (q >= 1) mbar_wait(mbE + s*8, (q-1) & 1);
                uint32_t stg = smem_u32 + s*STAGE_BYTES;
                mbar_expect(mbF + s*8, STAGE_BYTES);
                bulk_g2s(stg, Asrc + (size_t)kt*A_STG, A_STG, mbF + s*8);
                if (paired){
                    bulk_g2s_mc(stg + A_STG + rank*B_HALF,
                                Bsrc + (size_t)kt*B_STG + rank*B_HALF,
                                B_HALF, mbF + s*8, 0x3);
                } else {
                    bulk_g2s(stg + A_STG, Bsrc + (size_t)kt*B_STG, B_STG, mbF + s*8);
                }
            }
        };
        if (tid == 0){ issue(0); issue(1); issue(2); }

        float acc[3][4];
        #pragma unroll
        for (int i = 0; i < 3; i++)
            #pragma unroll
            for (int j = 0; j < 4; j++) acc[i][j] = 0.f;

        const int rowA = wm*16 + (lane & 7) + (lane & 8);
        const int cbA  = lane >> 4;
        const int rowBl = lane & 7;
        const int cbB  = (lane >> 3) & 1;

        for (int kt = 0; kt < NK; kt++){
            int s = kt % NSTG;
            mbar_wait(mbF + s*8, (kt/NSTG) & 1);
            uint32_t sA = smem_u32 + s*STAGE_BYTES;
            uint32_t sB = sA + A_STG;
            #pragma unroll
            for (int k16 = 0; k16 < KC/16; k16++){
                int cb = k16*2;
                uint32_t aaddr = sA + rowA*128 + (((cb + cbA) ^ (rowA & 7)) << 4);
                uint32_t a0,a1,a2,a3;
                asm volatile("ldmatrix.sync.aligned.m8n8.x4.shared.b16 {%0,%1,%2,%3}, [%4];"
                             : "=r"(a0),"=r"(a1),"=r"(a2),"=r"(a3) : "r"(aaddr));
                #pragma unroll
                for (int nt = 0; nt < 3; nt++){
                    int rB = wn*24 + nt*8 + rowBl;
                    uint32_t baddr = sB + rB*128 + (((cb + cbB) ^ (rB & 7)) << 4);
                    uint32_t b0,b1;
                    asm volatile("ldmatrix.sync.aligned.m8n8.x2.shared.b16 {%0,%1}, [%2];"
                                 : "=r"(b0),"=r"(b1) : "r"(baddr));
                    asm volatile("mma.sync.aligned.m16n8k16.row.col.f32.f16.f16.f32 "
                                 "{%0,%1,%2,%3}, {%4,%5,%6,%7}, {%8,%9}, {%0,%1,%2,%3};"
                                 : "+f"(acc[nt][0]),"+f"(acc[nt][1]),"+f"(acc[nt][2]),"+f"(acc[nt][3])
                                 : "r"(a0),"r"(a1),"r"(a2),"r"(a3),"r"(b0),"r"(b1));
                }
            }
            __syncthreads();
            if (tid == 0){
                mbar_arrive(mbE + s*8);
                if (paired) mbar_arrive_peer(mbE + s*8, rank ^ 1);
                issue(kt + NSTG);
            }
        }

        float* ghs = (float*)smem;
        {
            int r0 = wm*16 + (lane >> 2);
            int colb = (lane & 3)*2;
            #pragma unroll
            for (int nt = 0; nt < 3; nt++){
                int ccol = wn*24 + nt*8 + colb;
                ghs[r0*104 + ccol]         = acc[nt][0];
                ghs[r0*104 + ccol + 1]     = acc[nt][1];
                ghs[(r0+8)*104 + ccol]     = acc[nt][2];
                ghs[(r0+8)*104 + ccol + 1] = acc[nt][3];
            }
        }
        __syncthreads();

        if (MODE == 0){
            for (int idx = tid; idx < TM*TN/4; idx += 256){
                int m = idx / 24, q = idx % 24;
                int nl = q*4;
                int mg = mt*TM + m;
                if (mg < bc){
                    int bidx = g_order[seg0 + mg];
                    int g = nl >> 5, jj = nl & 31;
                    int wrow = (g<<10) + j0 + jj;
                    float4 v = *(float4*)&ghs[m*104 + nl];
                    float4 bi = __ldg((const float4*)(b_ih + (size_t)c*G3H + wrow));
                    v.x += bi.x; v.y += bi.y; v.z += bi.z; v.w += bi.w;
                    if (g < 2){
                        float4 bh = __ldg((const float4*)(b_hh + (size_t)c*G3H + wrow));
                        v.x += bh.x; v.y += bh.y; v.z += bh.z; v.w += bh.w;
                    }
                    *(float4*)(g_gi + (size_t)bidx*G3H + wrow) = v;
                }
            }
        } else {
            const float* __restrict__ hc = (t & 1) ? g_hB : g_hA;
            float*       __restrict__ hn = (t & 1) ? g_hA : g_hB;
            char*        __restrict__ hPn = (t & 1) ? g_hPA : g_hPB;
            int m = tid >> 3, jj = (tid & 7)*4;
            int mg = mt*TM + m;
            if (mg < bc){
                int bidx = g_order[seg0 + mg];
                int j = j0 + jj;
                float4 ghr = *(float4*)&ghs[m*104 + jj];
                float4 ghz = *(float4*)&ghs[m*104 + 32 + jj];
                float4 ghn4 = *(float4*)&ghs[m*104 + 64 + jj];
                const float* gi = g_gi + (size_t)bidx*G3H;
                float4 gir = *(const float4*)(gi + j);
                float4 giz = *(const float4*)(gi + H + j);
                float4 gin = *(const float4*)(gi + 2*H + j);
                float4 bn  = __ldg((const float4*)(b_hh + (size_t)c*G3H + 2*H + j));
                float4 hold = *(const float4*)(hc + (size_t)bidx*H + j);
                float4 hv;
                {
                    float r0 = sigf(gir.x + ghr.x), z0 = sigf(giz.x + ghz.x);
                    float n0 = tanhfast(gin.x + r0*(ghn4.x + bn.x));
                    hv.x = (1.f - z0)*n0 + z0*hold.x;
                    float r1 = sigf(gir.y + ghr.y), z1 = sigf(giz.y + ghz.y);
                    float n1 = tanhfast(gin.y + r1*(ghn4.y + bn.y));
                    hv.y = (1.f - z1)*n1 + z1*hold.y;
                    float r2 = sigf(gir.z + ghr.z), z2 = sigf(giz.z + ghz.z);
                    float n2 = tanhfast(gin.z + r2*(ghn4.z + bn.z));
                    hv.z = (1.f - z2)*n2 + z2*hold.z;
                    float r3 = sigf(gir.w + ghr.w), z3 = sigf(giz.w + ghz.w);
                    float n3 = tanhfast(gin.w + r3*(ghn4.w + bn.w));
                    hv.w = (1.f - z3)*n3 + z3*hold.w;
                }
                *(float4*)(hn + (size_t)bidx*H + j) = hv;
                __stcs((float4*)(g_hs + ((size_t)t*BATCH + bidx)*H + j), hv);
                int kt = j >> 6, ch = (j >> 3) & 7, win = (j & 7)*2;
                __half2 p0 = __floats2half2_rn(hv.x, hv.y);
                __half2 p1 = __floats2half2_rn(hv.z, hv.w);
                uint2 pk; pk.x = *(uint32_t*)&p0; pk.y = *(uint32_t*)&p1;
                *(uint2*)(hPn + (size_t)((c*2+mt)*NK + kt)*A_STG + m*128 + ((ch ^ (m&7))<<4) + win) = pk;
            }
        }
    }

    CLUSTER_SYNC();
}

// ---------------- final transpose [T,B,H] -> [B,H,T] ----------------
__global__ void transpose_kernel(float* __restrict__ out){
    __shared__ float tile[NT*65];
    int b = blockIdx.y, j0 = blockIdx.x*64, tid = threadIdx.x;
    for (int idx = tid; idx < NT*64; idx += 256){
        int t = idx >> 6, jj = idx & 63;
        tile[t*65 + jj] = __ldcs(&g_hs[((size_t)t*BATCH + b)*H + j0 + jj]);
    }
    __syncthreads();
    for (int idx = tid; idx < NT*64; idx += 256){
        int jj = idx / NT, t = idx % NT;
        __stcs(&out[((size_t)b*H + j0 + jj)*NT + t], tile[t*65 + jj]);
    }
}

// ---------------- launch ----------------
extern "C" void kernel_launch(void* const* d_in, const int* in_sizes, int n_in,
                              void* d_out, int out_size)
{
    const float* x   = (const float*)d_in[0];
    const int*   cam = (const int*)  d_in[1];
    const float* Wih = (const float*)d_in[2];
    const float* Whh = (const float*)d_in[3];
    const float* bih = (const float*)d_in[4];
    const float* bhh = (const float*)d_in[5];
    float* out = (float*)d_out;

    cudaFuncSetAttribute(gemm_step_kernel<0>, cudaFuncAttributeMaxDynamicSharedMemorySize, SMEM_DYN);
    cudaFuncSetAttribute(gemm_step_kernel<1>, cudaFuncAttributeMaxDynamicSharedMemorySize, SMEM_DYN);
    cudaFuncSetAttribute(convert_pack_kernel, cudaFuncAttributeMaxDynamicSharedMemorySize, CV_SMEM);

    setup_kernel<<<1, 256>>>(cam);
    init_pack_kernel<<<512, 256>>>(x);
    convert_pack_kernel<<<CV_GRID, 256, CV_SMEM>>>(Wih, Whh);

    dim3 grid(32, MAXMT);
    gemm_step_kernel<0><<<grid, 256, SMEM_DYN>>>(bih, bhh, -1);
    for (int t = 0; t < NT; t++)
        gemm_step_kernel<1><<<grid, 256, SMEM_DYN>>>(bih, bhh, t);

    transpose_kernel<<<dim3(16, BATCH), 256>>>(out);
}

// round 17
// speedup vs baseline: 1.5989x; 1.0861x over previous
#include <cuda_runtime.h>
#include <cuda_fp16.h>
#include <math.h>
#include <stdint.h>

#define H     1024
#define BATCH 256
#define NCAM  15
#define NT    60
#define G3H   3072

#define TM 32
#define TJ 32
#define TN 96
#define KC 64
#define NK (H/KC)
#define NSTG 3
#define A_STG 4096
#define B_STG 12288
#define B_HALF 6144
#define STAGE_BYTES (A_STG + B_STG)       // 16KB
#define SMEM_MAIN (NSTG*STAGE_BYTES)
#define SMEM_DYN  (SMEM_MAIN + 64)
#define MAXMT 24

// ---------------- scratch (static device globals) ----------------
__device__ __align__(128) char g_Pwih[(size_t)NCAM*32*NK*B_STG];
__device__ __align__(128) char g_Pwhh[(size_t)NCAM*32*NK*B_STG];
__device__ __align__(128) char g_xpack[(size_t)NCAM*2*NK*A_STG];
__device__ __align__(128) char g_hPA [(size_t)NCAM*2*NK*A_STG];
__device__ __align__(128) char g_hPB [(size_t)NCAM*2*NK*A_STG];
__device__ __align__(128) float g_hA[BATCH*H];
__device__ __align__(128) float g_hB[BATCH*H];
__device__ __align__(128) float g_gi[(size_t)BATCH*G3H];   // gi + b_ih + b_hh(r,z)
__device__ __align__(128) float g_hs[(size_t)NT*BATCH*H];
__device__ int g_order[BATCH];
__device__ int g_seg[NCAM+1];
__device__ int g_mtile[MAXMT];    // packed (c<<1)|mt; pairs-first ordering
__device__ int g_nmt;

// ---------------- ptx helpers ----------------
__device__ __forceinline__ void mbar_init(uint32_t a, uint32_t cnt){
    asm volatile("mbarrier.init.shared.b64 [%0], %1;" :: "r"(a), "r"(cnt) : "memory");
}
__device__ __forceinline__ void mbar_expect(uint32_t a, uint32_t tx){
    asm volatile("mbarrier.arrive.expect_tx.shared.b64 _, [%0], %1;" :: "r"(a), "r"(tx) : "memory");
}
__device__ __forceinline__ void mbar_arrive(uint32_t a){
    asm volatile("mbarrier.arrive.shared.b64 _, [%0];" :: "r"(a) : "memory");
}
__device__ __forceinline__ void mbar_arrive_peer(uint32_t a, uint32_t rank){
    asm volatile("{\n\t.reg .b32 ra;\n\t"
                 "mapa.shared::cluster.u32 ra, %0, %1;\n\t"
                 "mbarrier.arrive.shared::cluster.b64 _, [ra];\n\t}"
                 :: "r"(a), "r"(rank) : "memory");
}
__device__ __forceinline__ void bulk_g2s(uint32_t dst, const void* src, uint32_t bytes, uint32_t mbar){
    asm volatile("cp.async.bulk.shared::cta.global.mbarrier::complete_tx::bytes [%0], [%1], %2, [%3];"
                 :: "r"(dst), "l"(src), "r"(bytes), "r"(mbar) : "memory");
}
__device__ __forceinline__ void bulk_g2s_mc(uint32_t dst, const void* src, uint32_t bytes,
                                            uint32_t mbar, uint16_t mask){
    asm volatile("cp.async.bulk.shared::cluster.global.mbarrier::complete_tx::bytes.multicast::cluster "
                 "[%0], [%1], %2, [%3], %4;"
                 :: "r"(dst), "l"(src), "r"(bytes), "r"(mbar), "h"(mask) : "memory");
}
__device__ __forceinline__ void mbar_wait(uint32_t a, uint32_t phase){
    asm volatile("{\n\t.reg .pred P;\n\t"
                 "WL_%=:\n\t"
                 "mbarrier.try_wait.parity.acquire.cta.shared::cta.b64 P, [%0], %1, 0x989680;\n\t"
                 "@P bra.uni WD_%=;\n\t"
                 "bra.uni WL_%=;\n\t"
                 "WD_%=:\n\t}"
                 :: "r"(a), "r"(phase) : "memory");
}
#define CLUSTER_SYNC() do { \
    asm volatile("barrier.cluster.arrive.aligned;" ::: "memory"); \
    asm volatile("barrier.cluster.wait.aligned;" ::: "memory"); \
} while(0)
__device__ __forceinline__ float sigf(float x){ return 1.f/(1.f + __expf(-x)); }
__device__ __forceinline__ float tanhfast(float x){ return 2.f/(1.f + __expf(-2.f*x)) - 1.f; }

// ---------------- setup: group by camera + pairs-first mtile table ----------------
__global__ void setup_kernel(const int* __restrict__ cam){
    __shared__ int cnt[NCAM], offs[NCAM];
    int tid = threadIdx.x;
    if (tid < NCAM) cnt[tid] = 0;
    __syncthreads();
    int c = cam[tid];
    atomicAdd(&cnt[c], 1);
    __syncthreads();
    if (tid == 0){
        int s = 0;
        for (int i = 0; i < NCAM; i++){ offs[i] = s; g_seg[i] = s; s += cnt[i]; }
        g_seg[NCAM] = s;
        int nm = 0;
        for (int i = 0; i < NCAM; i++){
            if (cnt[i] > TM && nm + 1 < MAXMT){
                g_mtile[nm++] = (i << 1) | 0;
                g_mtile[nm++] = (i << 1) | 1;
            }
        }
        for (int i = 0; i < NCAM; i++){
            if (cnt[i] > 0 && cnt[i] <= TM && nm < MAXMT)
                g_mtile[nm++] = (i << 1) | 0;
        }
        g_nmt = nm;
        for (int k = nm; k < MAXMT; k++) g_mtile[k] = -1;
    }
    __syncthreads();
    int p = atomicAdd(&offs[c], 1);
    g_order[p] = tid;
}

// ---------------- init: pack x (sorted+swizzled), zero hP/hA ----------------
#define XCH   (NCAM*2*NK*256)
#define HPCH  (NCAM*2*NK*256)
__global__ void init_pack_kernel(const float* __restrict__ x){
    const int total = XCH + 2*HPCH + BATCH*H/4;
    int stride = gridDim.x*blockDim.x;
    for (int i = blockIdx.x*blockDim.x + threadIdx.x; i < total; i += stride){
        if (i < XCH){
            int blk = i >> 8, cin = i & 255;
            int r = cin >> 3, ch = cin & 7;
            int kt = blk & 15, cm = blk >> 4;
            int mt = cm & 1, c = cm >> 1;
            int seg0 = g_seg[c], bc = g_seg[c+1]-seg0;
            int mg = mt*TM + r;
            uint4 v = make_uint4(0,0,0,0);
            if (mg < bc){
                int bidx = g_order[seg0+mg];
                const float4* s = (const float4*)(x + (size_t)bidx*H + kt*KC + ch*8);
                float4 a = s[0], b = s[1];
                __half2 h0 = __floats2half2_rn(a.x,a.y), h1 = __floats2half2_rn(a.z,a.w);
                __half2 h2 = __floats2half2_rn(b.x,b.y), h3 = __floats2half2_rn(b.z,b.w);
                v.x = *(uint32_t*)&h0; v.y = *(uint32_t*)&h1;
                v.z = *(uint32_t*)&h2; v.w = *(uint32_t*)&h3;
            }
            *(uint4*)(g_xpack + (size_t)blk*A_STG + r*128 + ((ch ^ (r&7))<<4)) = v;
        } else if (i < XCH + 2*HPCH){
            int k = i - XCH;
            if (k < HPCH) ((uint4*)g_hPA)[k] = make_uint4(0,0,0,0);
            else          ((uint4*)g_hPB)[k-HPCH] = make_uint4(0,0,0,0);
        } else {
            int k = i - XCH - 2*HPCH;
            ((float4*)g_hA)[k] = make_float4(0.f,0.f,0.f,0.f);
        }
    }
}

// ---------------- convert + pack weights fp32 -> fp16 swizzled tiles ----------------
__global__ void convert_pack_kernel(const float* __restrict__ wi, const float* __restrict__ wh){
    const size_t NCH = (size_t)NCAM*32*NK*768;
    size_t stride = (size_t)gridDim.x*blockDim.x;
    for (size_t i = (size_t)blockIdx.x*blockDim.x + threadIdx.x; i < NCH; i += stride){
        size_t blk = i / 768; int cin = (int)(i % 768);
        int r = cin >> 3, ch = cin & 7;
        int kt = (int)(blk & 15); size_t cj = blk >> 4;
        int jt = (int)(cj & 31); int c = (int)(cj >> 5);
        int grow = ((r>>5)<<10) + jt*TJ + (r & 31);
        size_t src = (((size_t)c*G3H + grow)<<10) + kt*KC + ch*8;
        size_t dst = blk*B_STG + r*128 + ((ch ^ (r&7))<<4);
        {
            const float4* s = (const float4*)(wi + src);
            float4 a = __ldcs(s), b = __ldcs(s+1);
            __half2 h0 = __floats2half2_rn(a.x,a.y), h1 = __floats2half2_rn(a.z,a.w);
            __half2 h2 = __floats2half2_rn(b.x,b.y), h3 = __floats2half2_rn(b.z,b.w);
            uint4 v; v.x=*(uint32_t*)&h0; v.y=*(uint32_t*)&h1; v.z=*(uint32_t*)&h2; v.w=*(uint32_t*)&h3;
            __stcs((uint4*)(g_Pwih + dst), v);
        }
        {
            const float4* s = (const float4*)(wh + src);
            float4 a = __ldcs(s), b = __ldcs(s+1);
            __half2 h0 = __floats2half2_rn(a.x,a.y), h1 = __floats2half2_rn(a.z,a.w);
            __half2 h2 = __floats2half2_rn(b.x,b.y), h3 = __floats2half2_rn(b.z,b.w);
            uint4 v; v.x=*(uint32_t*)&h0; v.y=*(uint32_t*)&h1; v.z=*(uint32_t*)&h2; v.w=*(uint32_t*)&h3;
            *(uint4*)(g_Pwhh + dst) = v;
        }
    }
}

// ---------------- clustered bulk-fed GEMM + fused GRU epilogue ----------------
// CLUSTER_SYNC only when the pair-multicast path is live (paired). The decision
// is symmetric across the y-pair (same g_mtile reads), so both members agree.
template<int MODE>
__global__ void __launch_bounds__(256, 4) __cluster_dims__(1, 2, 1)
gemm_step_kernel(const float* __restrict__ b_ih, const float* __restrict__ b_hh, int t)
{
    extern __shared__ __align__(128) char smem[];
    const int jt = blockIdx.x;
    const int y  = blockIdx.y;
    const int rank = y & 1;
    const int cm  = g_mtile[y];
    const int cmp = g_mtile[y ^ 1];
    const bool active = (cm >= 0);
    const bool paired = active && (cmp >= 0) && ((cm >> 1) == (cmp >> 1));

    const int tid  = threadIdx.x;
    uint32_t smem_u32 = (uint32_t)__cvta_generic_to_shared(smem);
    uint32_t mbF = smem_u32 + SMEM_MAIN;
    uint32_t mbE = mbF + 24;

    if (tid == 0){
        uint32_t ecnt = paired ? 2u : 1u;
        #pragma unroll
        for (int s = 0; s < NSTG; s++){ mbar_init(mbF + s*8, 1); mbar_init(mbE + s*8, ecnt); }
        asm volatile("fence.proxy.async.shared::cta;" ::: "memory");
    }
    __syncthreads();
    if (paired) CLUSTER_SYNC();   // cross-CTA barriers only needed for multicast

    if (active){
        const int c  = cm >> 1;
        const int mt = cm & 1;
        const int seg0 = g_seg[c];
        const int bc   = g_seg[c+1] - seg0;

        const char* __restrict__ Apack = (MODE==0) ? g_xpack : ((t & 1) ? g_hPB : g_hPA);
        const char* __restrict__ Bpack = (MODE==0) ? g_Pwih : g_Pwhh;
        const char* Asrc = Apack + (size_t)((c*2+mt)*NK)*A_STG;
        const char* Bsrc = Bpack + (size_t)((c*32+jt)*NK)*B_STG;

        const int j0   = jt*TJ;
        const int lane = tid & 31, warp = tid >> 5;
        const int wm = warp & 1, wn = warp >> 1;

        auto issue = [&](int kt){
            if (kt < NK){
                int s = kt % NSTG, q = kt / NSTG;
                if (q >= 1) mbar_wait(mbE + s*8, (q-1) & 1);
                uint32_t stg = smem_u32 + s*STAGE_BYTES;
                mbar_expect(mbF + s*8, STAGE_BYTES);
                bulk_g2s(stg, Asrc + (size_t)kt*A_STG, A_STG, mbF + s*8);
                if (paired){
                    bulk_g2s_mc(stg + A_STG + rank*B_HALF,
                                Bsrc + (size_t)kt*B_STG + rank*B_HALF,
                                B_HALF, mbF + s*8, 0x3);
                } else {
                    bulk_g2s(stg + A_STG, Bsrc + (size_t)kt*B_STG, B_STG, mbF + s*8);
                }
            }
        };
        if (tid == 0){ issue(0); issue(1); issue(2); }

        float acc[3][4];
        #pragma unroll
        for (int i = 0; i < 3; i++)
            #pragma unroll
            for (int j = 0; j < 4; j++) acc[i][j] = 0.f;

        const int rowA = wm*16 + (lane & 7) + (lane & 8);
        const int cbA  = lane >> 4;
        const int rowBl = lane & 7;
        const int cbB  = (lane >> 3) & 1;

        for (int kt = 0; kt < NK; kt++){
            int s = kt % NSTG;
            mbar_wait(mbF + s*8, (kt/NSTG) & 1);
            uint32_t sA = smem_u32 + s*STAGE_BYTES;
            uint32_t sB = sA + A_STG;
            #pragma unroll
            for (int k16 = 0; k16 < KC/16; k16++){
                int cb = k16*2;
                uint32_t aaddr = sA + rowA*128 + (((cb + cbA) ^ (rowA & 7)) << 4);
                uint32_t a0,a1,a2,a3;
                asm volatile("ldmatrix.sync.aligned.m8n8.x4.shared.b16 {%0,%1,%2,%3}, [%4];"
                             : "=r"(a0),"=r"(a1),"=r"(a2),"=r"(a3) : "r"(aaddr));
                #pragma unroll
                for (int nt = 0; nt < 3; nt++){
                    int rB = wn*24 + nt*8 + rowBl;
                    uint32_t baddr = sB + rB*128 + (((cb + cbB) ^ (rB & 7)) << 4);
                    uint32_t b0,b1;
                    asm volatile("ldmatrix.sync.aligned.m8n8.x2.shared.b16 {%0,%1}, [%2];"
                                 : "=r"(b0),"=r"(b1) : "r"(baddr));
                    asm volatile("mma.sync.aligned.m16n8k16.row.col.f32.f16.f16.f32 "
                                 "{%0,%1,%2,%3}, {%4,%5,%6,%7}, {%8,%9}, {%0,%1,%2,%3};"
                                 : "+f"(acc[nt][0]),"+f"(acc[nt][1]),"+f"(acc[nt][2]),"+f"(acc[nt][3])
                                 : "r"(a0),"r"(a1),"r"(a2),"r"(a3),"r"(b0),"r"(b1));
                }
            }
            __syncthreads();
            if (tid == 0){
                mbar_arrive(mbE + s*8);
                if (paired) mbar_arrive_peer(mbE + s*8, rank ^ 1);
                issue(kt + NSTG);
            }
        }

        float* ghs = (float*)smem;
        {
            int r0 = wm*16 + (lane >> 2);
            int colb = (lane & 3)*2;
            #pragma unroll
            for (int nt = 0; nt < 3; nt++){
                int ccol = wn*24 + nt*8 + colb;
                ghs[r0*104 + ccol]         = acc[nt][0];
                ghs[r0*104 + ccol + 1]     = acc[nt][1];
                ghs[(r0+8)*104 + ccol]     = acc[nt][2];
                ghs[(r0+8)*104 + ccol + 1] = acc[nt][3];
            }
        }
        __syncthreads();

        if (MODE == 0){
            for (int idx = tid; idx < TM*TN/4; idx += 256){
                int m = idx / 24, q = idx % 24;
                int nl = q*4;
                int mg = mt*TM + m;
                if (mg < bc){
                    int bidx = g_order[seg0 + mg];
                    int g = nl >> 5, jj = nl & 31;
                    int wrow = (g<<10) + j0 + jj;
                    float4 v = *(float4*)&ghs[m*104 + nl];
                    float4 bi = __ldg((const float4*)(b_ih + (size_t)c*G3H + wrow));
                    v.x += bi.x; v.y += bi.y; v.z += bi.z; v.w += bi.w;
                    if (g < 2){
                        float4 bh = __ldg((const float4*)(b_hh + (size_t)c*G3H + wrow));
                        v.x += bh.x; v.y += bh.y; v.z += bh.z; v.w += bh.w;
                    }
                    *(float4*)(g_gi + (size_t)bidx*G3H + wrow) = v;
                }
            }
        } else {
            const float* __restrict__ hc = (t & 1) ? g_hB : g_hA;
            float*       __restrict__ hn = (t & 1) ? g_hA : g_hB;
            char*        __restrict__ hPn = (t & 1) ? g_hPA : g_hPB;
            int m = tid >> 3, jj = (tid & 7)*4;
            int mg = mt*TM + m;
            if (mg < bc){
                int bidx = g_order[seg0 + mg];
                int j = j0 + jj;
                float4 ghr = *(float4*)&ghs[m*104 + jj];
                float4 ghz = *(float4*)&ghs[m*104 + 32 + jj];
                float4 ghn4 = *(float4*)&ghs[m*104 + 64 + jj];
                const float* gi = g_gi + (size_t)bidx*G3H;
                float4 gir = *(const float4*)(gi + j);
                float4 giz = *(const float4*)(gi + H + j);
                float4 gin = *(const float4*)(gi + 2*H + j);
                float4 bn  = __ldg((const float4*)(b_hh + (size_t)c*G3H + 2*H + j));
                float4 hold = *(const float4*)(hc + (size_t)bidx*H + j);
                float4 hv;
                {
                    float r0 = sigf(gir.x + ghr.x), z0 = sigf(giz.x + ghz.x);
                    float n0 = tanhfast(gin.x + r0*(ghn4.x + bn.x));
                    hv.x = (1.f - z0)*n0 + z0*hold.x;
                    float r1 = sigf(gir.y + ghr.y), z1 = sigf(giz.y + ghz.y);
                    float n1 = tanhfast(gin.y + r1*(ghn4.y + bn.y));
                    hv.y = (1.f - z1)*n1 + z1*hold.y;
                    float r2 = sigf(gir.z + ghr.z), z2 = sigf(giz.z + ghz.z);
                    float n2 = tanhfast(gin.z + r2*(ghn4.z + bn.z));
                    hv.z = (1.f - z2)*n2 + z2*hold.z;
                    float r3 = sigf(gir.w + ghr.w), z3 = sigf(giz.w + ghz.w);
                    float n3 = tanhfast(gin.w + r3*(ghn4.w + bn.w));
                    hv.w = (1.f - z3)*n3 + z3*hold.w;
                }
                *(float4*)(hn + (size_t)bidx*H + j) = hv;
                __stcs((float4*)(g_hs + ((size_t)t*BATCH + bidx)*H + j), hv);
                int kt = j >> 6, ch = (j >> 3) & 7, win = (j & 7)*2;
                __half2 p0 = __floats2half2_rn(hv.x, hv.y);
                __half2 p1 = __floats2half2_rn(hv.z, hv.w);
                uint2 pk; pk.x = *(uint32_t*)&p0; pk.y = *(uint32_t*)&p1;
                *(uint2*)(hPn + (size_t)((c*2+mt)*NK + kt)*A_STG + m*128 + ((ch ^ (m&7))<<4) + win) = pk;
            }
        }
    }

    // only multicast traffic requires holding CTAs alive for each other
    if (paired) CLUSTER_SYNC();
}

// ---------------- final transpose [T,B,H] -> [B,H,T] ----------------
__global__ void transpose_kernel(float* __restrict__ out){
    __shared__ float tile[NT*65];
    int b = blockIdx.y, j0 = blockIdx.x*64, tid = threadIdx.x;
    for (int idx = tid; idx < NT*64; idx += 256){
        int t = idx >> 6, jj = idx & 63;
        tile[t*65 + jj] = __ldcs(&g_hs[((size_t)t*BATCH + b)*H + j0 + jj]);
    }
    __syncthreads();
    for (int idx = tid; idx < NT*64; idx += 256){
        int jj = idx / NT, t = idx % NT;
        __stcs(&out[((size_t)b*H + j0 + jj)*NT + t], tile[t*65 + jj]);
    }
}

// ---------------- launch ----------------
extern "C" void kernel_launch(void* const* d_in, const int* in_sizes, int n_in,
                              void* d_out, int out_size)
{
    const float* x   = (const float*)d_in[0];
    const int*   cam = (const int*)  d_in[1];
    const float* Wih = (const float*)d_in[2];
    const float* Whh = (const float*)d_in[3];
    const float* bih = (const float*)d_in[4];
    const float* bhh = (const float*)d_in[5];
    float* out = (float*)d_out;

    cudaFuncSetAttribute(gemm_step_kernel<0>, cudaFuncAttributeMaxDynamicSharedMemorySize, SMEM_DYN);
    cudaFuncSetAttribute(gemm_step_kernel<1>, cudaFuncAttributeMaxDynamicSharedMemorySize, SMEM_DYN);

    setup_kernel<<<1, 256>>>(cam);
    init_pack_kernel<<<512, 256>>>(x);
    convert_pack_kernel<<<4096, 256>>>(Wih, Whh);

    dim3 grid(32, MAXMT);
    gemm_step_kernel<0><<<grid, 256, SMEM_DYN>>>(bih, bhh, -1);
    for (int t = 0; t < NT; t++)
        gemm_step_kernel<1><<<grid, 256, SMEM_DYN>>>(bih, bhh, t);

    transpose_kernel<<<dim3(16, BATCH), 256>>>(out);
}